// round 15
// baseline (speedup 1.0000x reference)
#include <cuda_runtime.h>
#include <math.h>

#define H      768
#define BATCH  16
#define SEQ    4096
#define NCHUNK 18
#define CHUNK  228                 // 18*228 >= 4096; 228/4 = 57 tokens per warp
#define TPW    (CHUNK / 4)         // 57
#define NT     128                 // 4 warps per block
#define NWP    4
#define SCALE  0.03608439182435161f  // 768^-0.5
#define KSPLA  12                  // layer-A k-split (KC=192)
#define KSPLB  6                   // layer-B k-split (KC=128)
#define NJT    (H / 64)            // 12 j-tiles

// ---------------- scratch (static device arrays, allowed) ----------------
__device__ float g_psum [BATCH][NCHUNK][H];
__device__ float g_pmax [BATCH][NCHUNK][H];
__device__ float g_pmin [BATCH][NCHUNK][H];
__device__ float g_pacc0[BATCH][NCHUNK][H];
__device__ float g_pacc1[BATCH][NCHUNK][H];
__device__ float g_pl   [BATCH][NCHUNK][2];
__device__ float g_pooled[2][BATCH][3 * H];
__device__ float g_hid   [2][BATCH][H];
__device__ float g_partA [2][KSPLA][BATCH][H];
__device__ float g_partB [2][KSPLB][BATCH][H];
__device__ unsigned g_cntM[BATCH];    // self-resetting last-block counters
__device__ unsigned g_cntA[2][NJT];
__device__ unsigned g_cntB[2][NJT];

// ---------------- per-token work: one warp, whole token, NO barriers ----------------
// x[6]: lane's slice (h = i*128 + lane*4). All-lane redundant stage B (MUFU cost is
// per warp-instruction, so redundancy is free). No softmax max-shift: |z| << 1 here,
// shift is an exact identity and exp cannot overflow.
__device__ __forceinline__ void do_token(
    const float4* __restrict__ x,
    const float4* __restrict__ qg0s, const float4* __restrict__ qg1s,
    float S0, float S1, float C0, float C1,
    float4* accS, float4* accMx, float4* accMn, float4* acc0p, float4* acc1p,
    float& l0, float& K0, float& l1, float& K1)
{
    float sx = 0.f, sq = 0.f, d0 = 0.f, d1 = 0.f;
#pragma unroll
    for (int i = 0; i < 6; i++) {
        float4 xx = x[i];
        sx += (xx.x + xx.y) + (xx.z + xx.w);
        sq = fmaf(xx.x, xx.x, fmaf(xx.y, xx.y, fmaf(xx.z, xx.z, fmaf(xx.w, xx.w, sq))));
        float4 a = qg0s[i];
        d0 = fmaf(a.x, xx.x, fmaf(a.y, xx.y, fmaf(a.z, xx.z, fmaf(a.w, xx.w, d0))));
        float4 bq = qg1s[i];
        d1 = fmaf(bq.x, xx.x, fmaf(bq.y, xx.y, fmaf(bq.z, xx.z, fmaf(bq.w, xx.w, d1))));
    }
#pragma unroll
    for (int o = 16; o > 0; o >>= 1) {
        sx += __shfl_xor_sync(0xffffffffu, sx, o);
        sq += __shfl_xor_sync(0xffffffffu, sq, o);
        d0 += __shfl_xor_sync(0xffffffffu, d0, o);
        d1 += __shfl_xor_sync(0xffffffffu, d1, o);
    }
    float mu   = sx * (1.f / H);
    float var  = sq * (1.f / H) - mu * mu;
    float rstd = rsqrtf(var + 1e-5f);
    float z0 = (rstd * (d0 - mu * S0) + C0) * SCALE;
    float z1 = (rstd * (d1 - mu * S1) + C1) * SCALE;
    float w0 = __expf(z0), w1 = __expf(z1);
    float c0 = w0 * rstd, c1 = w1 * rstd;
    l0 += w0; K0 += c0 * mu;
    l1 += w1; K1 += c1 * mu;
#pragma unroll
    for (int i = 0; i < 6; i++) {
        float4 xx = x[i];
        accS[i].x += xx.x; accS[i].y += xx.y; accS[i].z += xx.z; accS[i].w += xx.w;
        accMx[i].x = fmaxf(accMx[i].x, xx.x); accMx[i].y = fmaxf(accMx[i].y, xx.y);
        accMx[i].z = fmaxf(accMx[i].z, xx.z); accMx[i].w = fmaxf(accMx[i].w, xx.w);
        accMn[i].x = fminf(accMn[i].x, xx.x); accMn[i].y = fminf(accMn[i].y, xx.y);
        accMn[i].z = fminf(accMn[i].z, xx.z); accMn[i].w = fminf(accMn[i].w, xx.w);
        acc0p[i].x = fmaf(c0, xx.x, acc0p[i].x); acc0p[i].y = fmaf(c0, xx.y, acc0p[i].y);
        acc0p[i].z = fmaf(c0, xx.z, acc0p[i].z); acc0p[i].w = fmaf(c0, xx.w, acc0p[i].w);
        acc1p[i].x = fmaf(c1, xx.x, acc1p[i].x); acc1p[i].y = fmaf(c1, xx.y, acc1p[i].y);
        acc1p[i].z = fmaf(c1, xx.z, acc1p[i].z); acc1p[i].w = fmaf(c1, xx.w, acc1p[i].w);
    }
}

// ---------------- kernel 1: warp-per-token fused pass, last-block combine -----------
__global__ __launch_bounds__(NT, 2) void main_pass(
    const float* __restrict__ tokens, const int* __restrict__ lengths,
    const float* __restrict__ q, const float* __restrict__ ln_g,
    const float* __restrict__ ln_b)
{
    const int b = blockIdx.y, c = blockIdx.x, t = threadIdx.x;
    const int w = t >> 5, lane = t & 31;
    __shared__ float4 sbuf[NWP][192];   // cross-warp reduce buffer (12 KB)
    __shared__ float4 sscal[NWP];
    __shared__ float  sIL[2];
    __shared__ unsigned sLast;

    const int len = lengths[b];
    const int s0  = c * CHUNK;

    // per-lane parameter slices (identical across warps; each warp spans full H)
    float4 qg0s[6], qg1s[6];
    float S0, S1, C0, C1;
    {
        float a = 0.f, d = 0.f, e = 0.f, f = 0.f;
#pragma unroll
        for (int i = 0; i < 6; i++) {
            const int h = i * 128 + lane * 4;
            float4 g4 = *(const float4*)&ln_g[h];
            float4 b4 = *(const float4*)&ln_b[h];
            float4 q0 = *(const float4*)&q[h];
            float4 q1 = *(const float4*)&q[H + h];
            qg0s[i] = make_float4(q0.x * g4.x, q0.y * g4.y, q0.z * g4.z, q0.w * g4.w);
            qg1s[i] = make_float4(q1.x * g4.x, q1.y * g4.y, q1.z * g4.z, q1.w * g4.w);
            a += (qg0s[i].x + qg0s[i].y) + (qg0s[i].z + qg0s[i].w);
            d += (qg1s[i].x + qg1s[i].y) + (qg1s[i].z + qg1s[i].w);
            e = fmaf(q0.x, b4.x, fmaf(q0.y, b4.y, fmaf(q0.z, b4.z, fmaf(q0.w, b4.w, e))));
            f = fmaf(q1.x, b4.x, fmaf(q1.y, b4.y, fmaf(q1.z, b4.z, fmaf(q1.w, b4.w, f))));
        }
#pragma unroll
        for (int o = 16; o > 0; o >>= 1) {
            a += __shfl_xor_sync(0xffffffffu, a, o);
            d += __shfl_xor_sync(0xffffffffu, d, o);
            e += __shfl_xor_sync(0xffffffffu, e, o);
            f += __shfl_xor_sync(0xffffffffu, f, o);
        }
        S0 = a; S1 = d; C0 = e; C1 = f;   // full-H sums (each warp covers all h)
    }

    float4 accS[6], accMx[6], accMn[6], acc0p[6], acc1p[6];
#pragma unroll
    for (int i = 0; i < 6; i++) {
        accS[i]  = make_float4(0.f, 0.f, 0.f, 0.f);
        acc0p[i] = make_float4(0.f, 0.f, 0.f, 0.f);
        acc1p[i] = make_float4(0.f, 0.f, 0.f, 0.f);
        accMx[i] = make_float4(-INFINITY, -INFINITY, -INFINITY, -INFINITY);
        accMn[i] = make_float4( INFINITY,  INFINITY,  INFINITY,  INFINITY);
    }
    float l0 = 0.f, K0 = 0.f, l1 = 0.f, K1 = 0.f;

    // ---- warp-private token range: contiguous, fully valid, NO masks ----
    {
        const float* xbase = tokens + (size_t)b * (SEQ + 1) * H + H;
        const int ws0 = min(s0 + w * TPW, len);
        const int ws1 = min(s0 + (w + 1) * TPW, len);
        if (ws0 < ws1) {
            float4 xa[6], xb[6];
            const float* r0 = xbase + (size_t)ws0 * H + lane * 4;
#pragma unroll
            for (int i = 0; i < 6; i++) xa[i] = *(const float4*)(r0 + i * 128);
            for (int s = ws0; s < ws1; s += 2) {
                if (s + 1 < ws1) {
                    const float* r = xbase + (size_t)(s + 1) * H + lane * 4;
#pragma unroll
                    for (int i = 0; i < 6; i++) xb[i] = *(const float4*)(r + i * 128);
                }
                do_token(xa, qg0s, qg1s, S0, S1, C0, C1,
                         accS, accMx, accMn, acc0p, acc1p, l0, K0, l1, K1);
                if (s + 1 < ws1) {
                    if (s + 2 < ws1) {
                        const float* r = xbase + (size_t)(s + 2) * H + lane * 4;
#pragma unroll
                        for (int i = 0; i < 6; i++) xa[i] = *(const float4*)(r + i * 128);
                    }
                    do_token(xb, qg0s, qg1s, S0, S1, C0, C1,
                             accS, accMx, accMn, acc0p, acc1p, l0, K0, l1, K1);
                }
            }
        }
    }

    // ---- cross-warp scalar reduce ----
    if (lane == 0) sscal[w] = make_float4(l0, K0, l1, K1);
    __syncthreads();
    {
        float4 s0v = sscal[0], s1v = sscal[1], s2v = sscal[2], s3v = sscal[3];
        l0 = s0v.x + s1v.x + s2v.x + s3v.x;
        K0 = s0v.y + s1v.y + s2v.y + s3v.y;
        l1 = s0v.z + s1v.z + s2v.z + s3v.z;
        K1 = s0v.w + s1v.w + s2v.w + s3v.w;
    }
    if (t == 0) { g_pl[b][c][0] = l0; g_pl[b][c][1] = l1; }

    // ---- cross-warp vector reduces (5 rounds through sbuf) ----
    // j -> h0: i = j>>5, l = j&31, h0 = i*128 + l*4
#define XW_ROUND(SRC, COMBINE_INIT, COMBINE_OP, TRANSFORM, DSTARR)                     \
    {                                                                                  \
        __syncthreads();                                                               \
        _Pragma("unroll")                                                              \
        for (int i = 0; i < 6; i++) sbuf[w][i * 32 + lane] = SRC[i];                   \
        __syncthreads();                                                               \
        for (int j = t; j < 192; j += NT) {                                            \
            float4 s = sbuf[0][j];                                                     \
            _Pragma("unroll")                                                          \
            for (int ww = 1; ww < NWP; ww++) {                                         \
                float4 u = sbuf[ww][j];                                                \
                s.x = COMBINE_OP(s.x, u.x); s.y = COMBINE_OP(s.y, u.y);                \
                s.z = COMBINE_OP(s.z, u.z); s.w = COMBINE_OP(s.w, u.w);                \
            }                                                                          \
            const int h0 = ((j >> 5) << 7) + ((j & 31) << 2);                          \
            TRANSFORM;                                                                 \
            *(float4*)&DSTARR[b][c][h0] = s;                                           \
        }                                                                              \
    }
#define OP_ADD(a, b) ((a) + (b))
    XW_ROUND(accS,  0, OP_ADD, {}, g_psum)
    XW_ROUND(accMx, 0, fmaxf,  {}, g_pmax)
    XW_ROUND(accMn, 0, fminf,  {}, g_pmin)
    XW_ROUND(acc0p, 0, OP_ADD,
        { float4 g4 = *(const float4*)&ln_g[h0]; float4 b4 = *(const float4*)&ln_b[h0];
          s.x = fmaf(g4.x, s.x - K0, b4.x * l0); s.y = fmaf(g4.y, s.y - K0, b4.y * l0);
          s.z = fmaf(g4.z, s.z - K0, b4.z * l0); s.w = fmaf(g4.w, s.w - K0, b4.w * l0); },
        g_pacc0)
    XW_ROUND(acc1p, 0, OP_ADD,
        { float4 g4 = *(const float4*)&ln_g[h0]; float4 b4 = *(const float4*)&ln_b[h0];
          s.x = fmaf(g4.x, s.x - K1, b4.x * l1); s.y = fmaf(g4.y, s.y - K1, b4.y * l1);
          s.z = fmaf(g4.z, s.z - K1, b4.z * l1); s.w = fmaf(g4.w, s.w - K1, b4.w * l1); },
        g_pacc1)
    __syncthreads();

    // ---- last block of batch b: fused combine epilogue ----
    __threadfence();
    if (t == 0) {
        sLast = atomicAdd(&g_cntM[b], 1u);
        if (sLast == NCHUNK - 1) g_cntM[b] = 0;   // self-reset
    }
    __syncthreads();
    if (sLast != NCHUNK - 1) return;
    __threadfence();   // acquire other blocks' partials

    if (t < 32) {
        float l0c = (t < NCHUNK) ? g_pl[b][t][0] : 0.f;
        float l1c = (t < NCHUNK) ? g_pl[b][t][1] : 0.f;
#pragma unroll
        for (int o = 16; o > 0; o >>= 1) {
            l0c += __shfl_xor_sync(0xffffffffu, l0c, o);
            l1c += __shfl_xor_sync(0xffffffffu, l1c, o);
        }
        if (t == 0) { sIL[0] = 1.f / l0c; sIL[1] = 1.f / l1c; }
    }
    __syncthreads();
    {
        const float iL0 = sIL[0], iL1 = sIL[1];
        const float inv_len = 1.f / (float)len;
        for (int h0 = 4 * t; h0 < H; h0 += 4 * NT) {
            float4 sm = make_float4(0.f, 0.f, 0.f, 0.f);
            float4 a0 = sm, a1 = sm;
            float4 mx = make_float4(-INFINITY, -INFINITY, -INFINITY, -INFINITY);
            float4 mn = make_float4( INFINITY,  INFINITY,  INFINITY,  INFINITY);
#pragma unroll 2
            for (int cc = 0; cc < NCHUNK; cc++) {
                float4 u = *(const float4*)&g_psum[b][cc][h0];
                sm.x += u.x; sm.y += u.y; sm.z += u.z; sm.w += u.w;
                float4 vx = *(const float4*)&g_pmax[b][cc][h0];
                mx.x = fmaxf(mx.x, vx.x); mx.y = fmaxf(mx.y, vx.y);
                mx.z = fmaxf(mx.z, vx.z); mx.w = fmaxf(mx.w, vx.w);
                float4 vn = *(const float4*)&g_pmin[b][cc][h0];
                mn.x = fminf(mn.x, vn.x); mn.y = fminf(mn.y, vn.y);
                mn.z = fminf(mn.z, vn.z); mn.w = fminf(mn.w, vn.w);
                float4 p0 = *(const float4*)&g_pacc0[b][cc][h0];
                a0.x += p0.x; a0.y += p0.y; a0.z += p0.z; a0.w += p0.w;
                float4 p1 = *(const float4*)&g_pacc1[b][cc][h0];
                a1.x += p1.x; a1.y += p1.y; a1.z += p1.z; a1.w += p1.w;
            }
            sm.x *= inv_len; sm.y *= inv_len; sm.z *= inv_len; sm.w *= inv_len;
            a0.x *= iL0; a0.y *= iL0; a0.z *= iL0; a0.w *= iL0;
            a1.x *= iL1; a1.y *= iL1; a1.z *= iL1; a1.w *= iL1;
            *(float4*)&g_pooled[0][b][h0]         = sm;
            *(float4*)&g_pooled[0][b][H + h0]     = mx;
            *(float4*)&g_pooled[0][b][2 * H + h0] = mn;
            *(float4*)&g_pooled[1][b][h0]         = a0;
            *(float4*)&g_pooled[1][b][H + h0]     = a1;
            *(float4*)&g_pooled[1][b][2 * H + h0] =
                *(const float4*)&tokens[(size_t)b * (SEQ + 1) * H + h0];  // clf
        }
    }
}

// ---------------- split-K GEMM with last-block fused epilogue ----------------
template <int K, int KC, int KSPL, bool LAYERA>
__global__ __launch_bounds__(256) void gemm_part(
    const float* __restrict__ W0, const float* __restrict__ W1,
    const float* __restrict__ bias0, const float* __restrict__ bias1,
    float* __restrict__ out)
{
    __shared__ __align__(16) char smemBuf[32768];
    float (*sP)[20] = (float (*)[20])smemBuf;
    float4 (*sAcc)[16][16] = (float4 (*)[16][16])smemBuf;
    __shared__ unsigned sLast;

    const int br = blockIdx.z;
    const int jt = blockIdx.x;
    const int j0 = jt * 64;
    const int k0 = blockIdx.y * KC;
    const int t  = threadIdx.x;
    const float* W = br ? W1 : W0;
    const float* P = LAYERA ? &g_pooled[br][0][0] : &g_hid[br][0][0];

    for (int idx = t; idx < BATCH * KC; idx += 256) {
        int m = idx / KC, k = idx % KC;
        sP[k][m] = P[(size_t)m * K + k0 + k];
    }
    __syncthreads();

    const int jq = t & 15, jj = jq * 4;
    const int kg = t >> 4;
    const int kb = kg * (KC / 16);
    float4 acc[BATCH];
#pragma unroll
    for (int m = 0; m < BATCH; m++) acc[m] = make_float4(0.f, 0.f, 0.f, 0.f);

    const float* Wp = W + (size_t)(k0 + kb) * H + j0 + jj;
#pragma unroll
    for (int k = 0; k < KC / 16; k++) {
        const float4 w = *(const float4*)(Wp + (size_t)k * H);
        const float* prow = &sP[kb + k][0];
#pragma unroll
        for (int m4 = 0; m4 < BATCH; m4 += 4) {
            const float4 pv = *(const float4*)(prow + m4);
            float pm[4] = {pv.x, pv.y, pv.z, pv.w};
#pragma unroll
            for (int u = 0; u < 4; u++) {
                acc[m4 + u].x = fmaf(pm[u], w.x, acc[m4 + u].x);
                acc[m4 + u].y = fmaf(pm[u], w.y, acc[m4 + u].y);
                acc[m4 + u].z = fmaf(pm[u], w.z, acc[m4 + u].z);
                acc[m4 + u].w = fmaf(pm[u], w.w, acc[m4 + u].w);
            }
        }
    }
#pragma unroll
    for (int m = 0; m < BATCH; m++) {
        acc[m].x += __shfl_xor_sync(0xffffffffu, acc[m].x, 16);
        acc[m].y += __shfl_xor_sync(0xffffffffu, acc[m].y, 16);
        acc[m].z += __shfl_xor_sync(0xffffffffu, acc[m].z, 16);
        acc[m].w += __shfl_xor_sync(0xffffffffu, acc[m].w, 16);
    }
    __syncthreads();
    const int wrp = t >> 5, lane = t & 31;
    if (lane < 16) {
#pragma unroll
        for (int m = 0; m < BATCH; m++) sAcc[wrp][m][lane] = acc[m];
    }
    __syncthreads();
    {
        const int m = t >> 4, jq2 = t & 15;
        float4 s = make_float4(0.f, 0.f, 0.f, 0.f);
#pragma unroll
        for (int w = 0; w < 8; w++) {
            float4 u = sAcc[w][m][jq2];
            s.x += u.x; s.y += u.y; s.z += u.z; s.w += u.w;
        }
        float* part = LAYERA ? &g_partA[br][blockIdx.y][0][0] : &g_partB[br][blockIdx.y][0][0];
        *(float4*)&part[(size_t)m * H + j0 + jq2 * 4] = s;
    }

    // ---- last-block-done fused epilogue ----
    __threadfence();
    if (t == 0) {
        unsigned* cnt = LAYERA ? &g_cntA[br][jt] : &g_cntB[br][jt];
        sLast = atomicAdd(cnt, 1u);
        if (sLast == KSPL - 1) *cnt = 0;   // self-reset
    }
    __syncthreads();
    if (sLast == KSPL - 1) {
        __threadfence();
        const int m = t >> 4, jq2 = t & 15;
        const float* bias = br ? bias1 : bias0;
        float4 s = ((const float4*)&bias[j0])[jq2];
#pragma unroll
        for (int sl = 0; sl < KSPL; sl++) {
            const float* part = LAYERA ? &g_partA[br][sl][0][0] : &g_partB[br][sl][0][0];
            float4 u = *(const float4*)&part[(size_t)m * H + j0 + jq2 * 4];
            s.x += u.x; s.y += u.y; s.z += u.z; s.w += u.w;
        }
        if (LAYERA) {
            s.x = 0.5f * s.x * (1.f + erff(s.x * 0.7071067811865476f));
            s.y = 0.5f * s.y * (1.f + erff(s.y * 0.7071067811865476f));
            s.z = 0.5f * s.z * (1.f + erff(s.z * 0.7071067811865476f));
            s.w = 0.5f * s.w * (1.f + erff(s.w * 0.7071067811865476f));
            *(float4*)&g_hid[br][m][j0 + jq2 * 4] = s;
        } else {
            *(float4*)&out[(size_t)m * (2 * H) + br * H + j0 + jq2 * 4] = s;
        }
    }
}

// ---------------- launch ----------------
extern "C" void kernel_launch(void* const* d_in, const int* in_sizes, int n_in,
                              void* d_out, int out_size)
{
    const float* tokens = (const float*)d_in[0];
    const int*   lengths= (const int*)  d_in[1];
    const float* q      = (const float*)d_in[2];
    const float* ln_g   = (const float*)d_in[3];
    const float* ln_b   = (const float*)d_in[4];
    const float* w1a    = (const float*)d_in[5];
    const float* b1a    = (const float*)d_in[6];
    const float* w1b    = (const float*)d_in[7];
    const float* b1b    = (const float*)d_in[8];
    const float* w2a    = (const float*)d_in[9];
    const float* b2a    = (const float*)d_in[10];
    const float* w2b    = (const float*)d_in[11];
    const float* b2b    = (const float*)d_in[12];
    float* out = (float*)d_out;

    main_pass<<<dim3(NCHUNK, BATCH), NT>>>(tokens, lengths, q, ln_g, ln_b);
    gemm_part<3 * H, 3 * H / KSPLA, KSPLA, true >
        <<<dim3(NJT, KSPLA, 2), 256>>>(w1a, w2a, b1a, b2a, nullptr);
    gemm_part<H, H / KSPLB, KSPLB, false>
        <<<dim3(NJT, KSPLB, 2), 256>>>(w1b, w2b, b1b, b2b, out);
}